// round 8
// baseline (speedup 1.0000x reference)
#include <cuda_runtime.h>
#include <cstdint>

// ConvTranspose2d(64->64,k4,s2,p1)+bias+mish+(+0.5,clip,*2) via mma.sync tf32.
// y[p,oc] = sum_k A[p,k]*B[oc,k], k = (b*2+a)*64 + ic, K=256.
//   pixel p=(ohi,m): oh = ph+4t+2*ohi, ow = 2m+pw ; Rb = 2t+ph
//   A[p,k] = x[n, ic, Rb+ohi-a, m+pw-b]   (zero OOB)
//   B[oc,k] = w[oc, ic, (1-ph)+2a, (1-pw)+2b]
// CTA = (ph, ocH): all 256 px (2 pw), 32 oc. 256 thr, 8 warps = (pw, mq),
// warp tile 32px x 32oc (LDSM:MMA = 0.5). SMEM 115.2KB -> 2 CTAs/SM.
// xT: 193 rows x 256B (row = r*64 + j, ic-major), 16B-chunk XOR swizzle by
// (row&15) -> conflict-free ldsm; OOB j remapped per-lane to zero row 192.
// Persistent: 296 CTAs, 74 slots x ~27.7 tiles (n,t).

#define NT 256
#define SM_B    256
#define SM_XT   (SM_B + 65536)            // 65792
#define ZROW    192
#define SMEM_TOTAL (SM_XT + 193 * 256)    // 115200 <= 115712 (2 CTAs/SM)

static __device__ __forceinline__ uint32_t s2u(const void* p) {
    uint32_t a;
    asm("{ .reg .u64 t; cvta.to.shared.u64 t, %1; cvt.u32.u64 %0, t; }" : "=r"(a) : "l"(p));
    return a;
}
static __device__ __forceinline__ uint32_t cvt_tf32(float f) {
    uint32_t r; asm("cvt.rn.tf32.f32 %0, %1;" : "=r"(r) : "f"(f)); return r;
}
static __device__ __forceinline__ void sts32(uint32_t addr, uint32_t v) {
    asm volatile("st.shared.b32 [%0], %1;" :: "r"(addr), "r"(v) : "memory");
}
static __device__ __forceinline__ void ldsm4(uint32_t* r, uint32_t addr) {
    asm volatile("ldmatrix.sync.aligned.m8n8.x4.shared.b16 {%0,%1,%2,%3}, [%4];"
                 : "=r"(r[0]), "=r"(r[1]), "=r"(r[2]), "=r"(r[3]) : "r"(addr));
}
static __device__ __forceinline__ void mma8(float* d, const uint32_t* a,
                                            uint32_t b0, uint32_t b1) {
    asm volatile("mma.sync.aligned.m16n8k8.row.col.f32.tf32.tf32.f32 "
                 "{%0,%1,%2,%3}, {%4,%5,%6,%7}, {%8,%9}, {%0,%1,%2,%3};"
                 : "+f"(d[0]), "+f"(d[1]), "+f"(d[2]), "+f"(d[3])
                 : "r"(a[0]), "r"(a[1]), "r"(a[2]), "r"(a[3]), "r"(b0), "r"(b1));
}

__device__ __forceinline__ float postop(float y) {
    // mish(y) = y*(t^2+2t)/(t^2+2t+2), t=e^y ; then +0.5, clip[-1,1], *2
    float t = __expf(fminf(y, 30.0f));
    float u = t * (t + 2.0f);
    float mish = y * __fdividef(u, u + 2.0f);
    float v = fminf(fmaxf(mish + 0.5f, -1.0f), 1.0f);
    return v * 2.0f;
}

__global__ __launch_bounds__(NT, 2)
void convt_mma_kernel(const float* __restrict__ x,
                      const float* __restrict__ weight,
                      const float* __restrict__ bias,
                      float* __restrict__ out) {
    extern __shared__ char smem[];
    const uint32_t sb = s2u(smem);
    const int tid  = threadIdx.x;
    const int warp = tid >> 5;
    const int lane = tid & 31;
    const int ph   = blockIdx.x & 1;
    const int ocH  = (blockIdx.x >> 1) & 1;
    const int slot = blockIdx.x >> 2;     // 0..73

    if (tid < 64) ((float*)smem)[tid] = bias[tid];

    // ---- stage B once: row = pw*32 + ocl (1024B), byte = k*4 ^ ((ocl&7)<<4) ----
    for (int it = 0; it < 64; it++) {
        int idx = tid + it * NT;          // 0..16383
        int pw  = idx >> 13;
        int ocl = (idx >> 8) & 31;
        int k   = idx & 255;
        int g = k >> 6, ic = k & 63, a = g & 1, b = g >> 1;
        int kh = (1 - ph) + 2 * a;
        int kw = (1 - pw) + 2 * b;
        float f = __ldg(weight + (((32 * ocH + ocl) * 64 + ic) << 4) + (kh << 2) + kw);
        uint32_t byte = ((uint32_t)(k << 2)) ^ ((uint32_t)(ocl & 7) << 4);
        sts32(sb + SM_B + (pw * 32 + ocl) * 1024 + byte, cvt_tf32(f));
    }
    // zero row (never overwritten: ys uses only 33792B of xT region)
    if (tid < 64) sts32(sb + SM_XT + ZROW * 256 + tid * 4, 0u);
    __syncthreads();

    // warp roles: pw (0..1) | mq (0..3)
    const int mq  = warp & 3;
    const int pw  = warp >> 2;
    const int p0  = 32 * mq;              // pixel base (p = ohi*64 + m)
    const int ohi = mq >> 1;
    const int msub0 = 32 * (mq & 1);

    // per-lane LDSM indices
    const int l15 = lane & 15;
    const int lhi = lane >> 4;
    const int oc_l = (lane & 7) + 8 * lhi;
    const uint32_t khalf = (uint32_t)((lane >> 3) & 1) << 4;
    const uint32_t swzB  = (uint32_t)(lane & 7) << 4;
    uint32_t rbB[2];
#pragma unroll
    for (int jp = 0; jp < 2; jp++)
        rbB[jp] = sb + SM_B + (uint32_t)(pw * 32 + 16 * jp + oc_l) * 1024;

    for (int widx = slot; widx < 2048; widx += 74) {
        const int n = widx >> 5;
        const int t = widx & 31;
        const int Rb = 2 * t + ph;
        const float* xn = x + (size_t)n * (64 * 64 * 64);

        // ---- stage xT: 192 rows (r*64+j) x 64 ic; byte = ic*4 ^ ((row&15)<<4) ----
#pragma unroll 1
        for (int it = 0; it < 48; it++) {
            int idx = tid + it * NT;           // 0..12287
            int j   = idx & 63;
            int t2  = idx >> 6;                // 0..191
            int ic  = t2 & 63;
            int r   = t2 >> 6;                 // 0..2
            int rg  = Rb - 1 + r;
            float v = 0.0f;
            if ((unsigned)rg < 64u)
                v = __ldg(xn + (ic * 64 + rg) * 64 + j);
            int row = r * 64 + j;
            uint32_t byte = ((uint32_t)(ic << 2)) ^ ((uint32_t)(row & 15) << 4);
            sts32(sb + SM_XT + row * 256 + byte, cvt_tf32(v));
        }
        __syncthreads();

        float acc[2][4][4];
#pragma unroll
        for (int i = 0; i < 2; i++)
#pragma unroll
            for (int j = 0; j < 4; j++)
#pragma unroll
                for (int e = 0; e < 4; e++) acc[i][j][e] = 0.0f;

#pragma unroll
        for (int g = 0; g < 4; g++) {
            const int a = g & 1, b = g >> 1;
            const int rowsel = ohi + 1 - a;
            const int jA = msub0 + pw - b + l15;        // j of first fragment
            const int rowL0 = ((unsigned)jA < 64u) ? rowsel * 64 + jA : ZROW;
            const int rowL1 = ((unsigned)(jA + 16) < 64u) ? rowsel * 64 + jA + 16 : ZROW;
            const uint32_t base0 = sb + SM_XT + (uint32_t)rowL0 * 256;
            const uint32_t base1 = sb + SM_XT + (uint32_t)rowL1 * 256;
            const uint32_t r0 = (uint32_t)(rowL0 & 15);
            const uint32_t r1 = (uint32_t)(rowL1 & 15);
            const uint32_t kb0 = ((uint32_t)g << 8) + khalf;

#pragma unroll
            for (int s8 = 0; s8 < 8; s8++) {
                const uint32_t ch = (uint32_t)(s8 << 1) + (uint32_t)lhi;
                uint32_t Af0[4], Af1[4];
                ldsm4(Af0, base0 + ((ch ^ r0) << 4));
                ldsm4(Af1, base1 + ((ch ^ r1) << 4));
                const uint32_t kb = (kb0 + ((uint32_t)s8 << 5)) ^ swzB;
                uint32_t Bf[2][4];
                ldsm4(Bf[0], rbB[0] + kb);
                ldsm4(Bf[1], rbB[1] + kb);
#pragma unroll
                for (int jp = 0; jp < 2; jp++) {
                    mma8(acc[0][2 * jp],     Af0, Bf[jp][0], Bf[jp][1]);
                    mma8(acc[0][2 * jp + 1], Af0, Bf[jp][2], Bf[jp][3]);
                    mma8(acc[1][2 * jp],     Af1, Bf[jp][0], Bf[jp][1]);
                    mma8(acc[1][2 * jp + 1], Af1, Bf[jp][2], Bf[jp][3]);
                }
            }
        }
        __syncthreads();   // xT dead; region becomes ys

        // ---- epilogue: postop -> ys[pw][ocl][132-padded p] (33792B, zero row safe) ----
        float* ysf = (float*)(smem + SM_XT);
        const float* bsm = (const float*)smem;
        const int gL = lane >> 2, tg = lane & 3;
#pragma unroll
        for (int i = 0; i < 2; i++) {
            const int prow = p0 + 16 * i + gL;
#pragma unroll
            for (int j = 0; j < 4; j++) {
                const int ocl = 8 * j + 2 * tg;
                const int oc  = 32 * ocH + ocl;
                const float b0v = bsm[oc], b1v = bsm[oc + 1];
                const int base = (pw * 32 + ocl) * 132;
                ysf[base + prow]           = postop(acc[i][j][0] + b0v);
                ysf[base + 132 + prow]     = postop(acc[i][j][1] + b1v);
                ysf[base + prow + 8]       = postop(acc[i][j][2] + b0v);
                ysf[base + 132 + prow + 8] = postop(acc[i][j][3] + b1v);
            }
        }
        __syncthreads();

        // ---- coalesced store: 2048 float4 ----
#pragma unroll
        for (int it = 0; it < 8; it++) {
            int vid = tid + it * NT;
            int ow4 = vid & 31;
            int row = vid >> 5;            // 0..63
            int oh2 = row & 1;
            int ocl = row >> 1;            // 0..31
            int m0  = 2 * ow4;
            int pb  = oh2 * 64;
            float4 v;
            v.x = ysf[(0 * 32 + ocl) * 132 + pb + m0];
            v.y = ysf[(1 * 32 + ocl) * 132 + pb + m0];
            v.z = ysf[(0 * 32 + ocl) * 132 + pb + m0 + 1];
            v.w = ysf[(1 * 32 + ocl) * 132 + pb + m0 + 1];
            int oh = ph + 4 * t + 2 * oh2;
            int oc = 32 * ocH + ocl;
            *(float4*)(out + (((size_t)n * 64 + oc) * 128 + oh) * 128 + 4 * ow4) = v;
        }
        __syncthreads();   // ys dead before next tile's xT staging
    }
}

extern "C" void kernel_launch(void* const* d_in, const int* in_sizes, int n_in,
                              void* d_out, int out_size) {
    const float* x      = (const float*)d_in[0];
    const float* weight = (const float*)d_in[1];
    const float* bias   = (const float*)d_in[2];
    float* out          = (float*)d_out;

    cudaFuncSetAttribute(convt_mma_kernel,
                         cudaFuncAttributeMaxDynamicSharedMemorySize, SMEM_TOTAL);
    convt_mma_kernel<<<296, NT, SMEM_TOTAL>>>(x, weight, bias, out);
}

// round 9
// speedup vs baseline: 1.5847x; 1.5847x over previous
#include <cuda_runtime.h>
#include <cstdint>

// ConvTranspose2d(64->64,k4,s2,p1)+bias+mish+(+0.5,clip,*2) via mma.sync tf32.
// y[p,oc] = sum_k A[p,k]*B[oc,k], k = (b*2+a)*64 + ic, K=256.
//   pixel p=(ohi,m): oh = ph+4t+2*ohi, ow = 2m+pw ; Rb = 2t+ph
//   A[p,k] = x[n, ic, Rb+ohi-a, m+pw-b]   (zero OOB)
//   B[oc,k] = w[oc, ic, (1-ph)+2a, (1-pw)+2b]
// CTA = (n, ph): 32 sequential tiles t. 5-slot input-row RING (slot = rg%5,
// rows 256B = 64 ic tf32, swizzle (j&15)<<4, OOB j -> ZROW). Per tile:
//   A: stage rows Rb+2,Rb+3 (next tile)  [slots Rb+2,Rb+3 mod 5]
//   B: mma from slots Rb-1,Rb,Rb+1       [disjoint -> NO barrier between A,B]
//   C: epilogue in 4 chunks of 16 oc through small ys (float4 stores).
// 512 thr, 16 warps = (pw, och, mq), warp tile 32px x 32oc.

#define NT 512
#define SM_B    256
#define SM_RING (SM_B + 131072)            // 131328
#define ZROW    320
#define SM_YS   (SM_RING + 321 * 256)      // 213504
#define SMEM_TOTAL (SM_YS + 16896)         // 230400

static __device__ __forceinline__ uint32_t s2u(const void* p) {
    uint32_t a;
    asm("{ .reg .u64 t; cvta.to.shared.u64 t, %1; cvt.u32.u64 %0, t; }" : "=r"(a) : "l"(p));
    return a;
}
static __device__ __forceinline__ uint32_t cvt_tf32(float f) {
    uint32_t r; asm("cvt.rn.tf32.f32 %0, %1;" : "=r"(r) : "f"(f)); return r;
}
static __device__ __forceinline__ void sts32(uint32_t addr, uint32_t v) {
    asm volatile("st.shared.b32 [%0], %1;" :: "r"(addr), "r"(v) : "memory");
}
static __device__ __forceinline__ void ldsm4(uint32_t* r, uint32_t addr) {
    asm volatile("ldmatrix.sync.aligned.m8n8.x4.shared.b16 {%0,%1,%2,%3}, [%4];"
                 : "=r"(r[0]), "=r"(r[1]), "=r"(r[2]), "=r"(r[3]) : "r"(addr));
}
static __device__ __forceinline__ void mma8(float* d, const uint32_t* a,
                                            uint32_t b0, uint32_t b1) {
    asm volatile("mma.sync.aligned.m16n8k8.row.col.f32.tf32.tf32.f32 "
                 "{%0,%1,%2,%3}, {%4,%5,%6,%7}, {%8,%9}, {%0,%1,%2,%3};"
                 : "+f"(d[0]), "+f"(d[1]), "+f"(d[2]), "+f"(d[3])
                 : "r"(a[0]), "r"(a[1]), "r"(a[2]), "r"(a[3]), "r"(b0), "r"(b1));
}

__device__ __forceinline__ float postop(float y) {
    // mish(y) = y*(t^2+2t)/(t^2+2t+2), t=e^y ; then +0.5, clip[-1,1], *2
    float t = __expf(fminf(y, 30.0f));
    float u = t * (t + 2.0f);
    float mish = y * __fdividef(u, u + 2.0f);
    float v = fminf(fmaxf(mish + 0.5f, -1.0f), 1.0f);
    return v * 2.0f;
}

__global__ __launch_bounds__(NT, 1)
void convt_mma_kernel(const float* __restrict__ x,
                      const float* __restrict__ weight,
                      const float* __restrict__ bias,
                      float* __restrict__ out) {
    extern __shared__ char smem[];
    const uint32_t sb = s2u(smem);
    const int tid  = threadIdx.x;
    const int warp = tid >> 5;
    const int lane = tid & 31;
    const int ph   = blockIdx.x & 1;
    const int n    = blockIdx.x >> 1;
    const float* xn = x + (size_t)n * (64 * 64 * 64);

    if (tid < 64) ((float*)smem)[tid] = bias[tid];

    // ---- stage B once: row = pw*64 + oc (1024B), byte = k*4 ^ ((oc&7)<<4) ----
    for (int it = 0; it < 64; it++) {
        int idx = tid + it * NT;          // 0..32767
        int pw = idx >> 14;
        int oc = (idx >> 8) & 63;
        int k  = idx & 255;
        int g = k >> 6, ic = k & 63, a = g & 1, b = g >> 1;
        int kh = (1 - ph) + 2 * a;
        int kw = (1 - pw) + 2 * b;
        float f = __ldg(weight + ((oc * 64 + ic) << 4) + (kh << 2) + kw);
        uint32_t byte = ((uint32_t)(k << 2)) ^ ((uint32_t)(oc & 7) << 4);
        sts32(sb + SM_B + (pw * 64 + oc) * 1024 + byte, cvt_tf32(f));
    }
    // zero row
    if (tid < 64) sts32(sb + SM_RING + ZROW * 256 + tid * 4, 0u);

    // ---- prologue: stage rows ph-1, ph, ph+1 into ring ----
#pragma unroll 4
    for (int it = 0; it < 24; it++) {
        int idx = tid + it * NT;           // 0..12287
        int j   = idx & 63;
        int ic  = (idx >> 6) & 63;
        int rr  = idx >> 12;               // 0..2
        int rg  = ph - 1 + rr;
        float v = 0.0f;
        if ((unsigned)rg < 64u) v = __ldg(xn + (ic * 64 + rg) * 64 + j);
        int row = ((rg + 5) % 5) * 64 + j;
        uint32_t byte = ((uint32_t)(ic << 2)) ^ ((uint32_t)(j & 15) << 4);
        sts32(sb + SM_RING + row * 256 + byte, cvt_tf32(v));
    }
    __syncthreads();

    // warp roles: pw | och | mq
    const int pw  = warp >> 3;
    const int och = (warp >> 2) & 1;
    const int mq  = warp & 3;
    const int p0  = 32 * mq;              // pixel base (p = ohi*64 + m)
    const int ohi = mq >> 1;
    const int msub0 = 32 * (mq & 1);

    const int l15 = lane & 15;
    const int lhi = lane >> 4;
    const int oc_l = (lane & 7) + 8 * lhi;
    const uint32_t khalf = (uint32_t)((lane >> 3) & 1) << 4;
    const uint32_t swzB  = (uint32_t)(lane & 7) << 4;
    uint32_t rbB[2];
#pragma unroll
    for (int jp = 0; jp < 2; jp++)
        rbB[jp] = sb + SM_B + (uint32_t)(pw * 64 + 32 * och + 16 * jp + oc_l) * 1024;

    const int gL = lane >> 2, tg = lane & 3;
    float* ysf = (float*)(smem + SM_YS);
    const float* bsm = (const float*)smem;

    for (int t = 0; t < 32; t++) {
        const int Rb = 2 * t + ph;

        // ---- phase A: stage rows Rb+2, Rb+3 (for tile t+1); no barrier before B ----
        if (t < 31) {
#pragma unroll 4
            for (int it = 0; it < 16; it++) {
                int idx = tid + it * NT;       // 0..8191
                int j   = idx & 63;
                int ic  = (idx >> 6) & 63;
                int rr  = idx >> 12;           // 0..1
                int rg  = Rb + 2 + rr;
                float v = 0.0f;
                if ((unsigned)rg < 64u) v = __ldg(xn + (ic * 64 + rg) * 64 + j);
                int row = ((rg + 5) % 5) * 64 + j;
                uint32_t byte = ((uint32_t)(ic << 2)) ^ ((uint32_t)(j & 15) << 4);
                sts32(sb + SM_RING + row * 256 + byte, cvt_tf32(v));
            }
        }

        // ---- phase B: compute from ring slots (Rb-1, Rb, Rb+1) ----
        float acc[2][4][4];
#pragma unroll
        for (int i = 0; i < 2; i++)
#pragma unroll
            for (int j = 0; j < 4; j++)
#pragma unroll
                for (int e = 0; e < 4; e++) acc[i][j][e] = 0.0f;

#pragma unroll
        for (int g = 0; g < 4; g++) {
            const int a = g & 1, b = g >> 1;
            const int rgA = Rb + ohi - a;                    // -1..64
            const int slotA = (rgA + 5) % 5;
            const int jA = msub0 + pw - b + l15;             // -1..64
            const int rowL0 = ((unsigned)jA < 64u) ? slotA * 64 + jA : ZROW;
            const int rowL1 = ((unsigned)(jA + 16) < 64u) ? slotA * 64 + jA + 16 : ZROW;
            const uint32_t base0 = sb + SM_RING + (uint32_t)rowL0 * 256;
            const uint32_t base1 = sb + SM_RING + (uint32_t)rowL1 * 256;
            const uint32_t r0 = (uint32_t)(rowL0 & 15);
            const uint32_t r1 = (uint32_t)(rowL1 & 15);
            const uint32_t kb0 = ((uint32_t)g << 8) + khalf;

#pragma unroll
            for (int s8 = 0; s8 < 8; s8++) {
                const uint32_t ch = (uint32_t)(s8 << 1) + (uint32_t)lhi;
                uint32_t Af0[4], Af1[4];
                ldsm4(Af0, base0 + ((ch ^ r0) << 4));
                ldsm4(Af1, base1 + ((ch ^ r1) << 4));
                const uint32_t kb = (kb0 + ((uint32_t)s8 << 5)) ^ swzB;
                uint32_t Bf[2][4];
                ldsm4(Bf[0], rbB[0] + kb);
                ldsm4(Bf[1], rbB[1] + kb);
#pragma unroll
                for (int jp = 0; jp < 2; jp++) {
                    mma8(acc[0][2 * jp],     Af0, Bf[jp][0], Bf[jp][1]);
                    mma8(acc[0][2 * jp + 1], Af0, Bf[jp][2], Bf[jp][3]);
                    mma8(acc[1][2 * jp],     Af1, Bf[jp][0], Bf[jp][1]);
                    mma8(acc[1][2 * jp + 1], Af1, Bf[jp][2], Bf[jp][3]);
                }
            }
        }

        // ---- phase C: epilogue, 4 chunks of 16 oc through ys ----
#pragma unroll 1
        for (int q = 0; q < 4; q++) {
            if (och == (q >> 1)) {
                const int jj = q & 1;
#pragma unroll
                for (int i = 0; i < 2; i++) {
                    const int prow = p0 + 16 * i + gL;
#pragma unroll
                    for (int j2 = 0; j2 < 2; j2++) {
                        const int j  = 2 * jj + j2;
                        const int ocl = 8 * j + 2 * tg;       // warp-local 0..31
                        const int oc  = 32 * och + ocl;
                        const int ocx = oc - 16 * q;          // 0..15
                        const float b0v = bsm[oc], b1v = bsm[oc + 1];
                        const int base = (pw * 16 + ocx) * 132;
                        ysf[base + prow]           = postop(acc[i][j][0] + b0v);
                        ysf[base + 132 + prow]     = postop(acc[i][j][1] + b1v);
                        ysf[base + prow + 8]       = postop(acc[i][j][2] + b0v);
                        ysf[base + 132 + prow + 8] = postop(acc[i][j][3] + b1v);
                    }
                }
            }
            __syncthreads();   // also orders phase-A ring writes before next tile's B
#pragma unroll
            for (int it = 0; it < 2; it++) {
                int vid = tid + it * NT;       // 0..1023
                int ow4 = vid & 31;
                int row = vid >> 5;            // 0..31
                int oh2 = row & 1;
                int ocx = row >> 1;            // 0..15
                int m0  = 2 * ow4;
                int pb  = oh2 * 64;
                float4 v;
                v.x = ysf[(0 * 16 + ocx) * 132 + pb + m0];
                v.y = ysf[(1 * 16 + ocx) * 132 + pb + m0];
                v.z = ysf[(0 * 16 + ocx) * 132 + pb + m0 + 1];
                v.w = ysf[(1 * 16 + ocx) * 132 + pb + m0 + 1];
                int oh = ph + 4 * t + 2 * oh2;
                int oc = 16 * q + ocx;
                *(float4*)(out + (((size_t)n * 64 + oc) * 128 + oh) * 128 + 4 * ow4) = v;
            }
            __syncthreads();   // ys consumed before next chunk overwrites
        }
    }
}

extern "C" void kernel_launch(void* const* d_in, const int* in_sizes, int n_in,
                              void* d_out, int out_size) {
    const float* x      = (const float*)d_in[0];
    const float* weight = (const float*)d_in[1];
    const float* bias   = (const float*)d_in[2];
    float* out          = (float*)d_out;

    cudaFuncSetAttribute(convt_mma_kernel,
                         cudaFuncAttributeMaxDynamicSharedMemorySize, SMEM_TOTAL);
    convt_mma_kernel<<<128, NT, SMEM_TOTAL>>>(x, weight, bias, out);
}

// round 10
// speedup vs baseline: 2.3198x; 1.4639x over previous
#include <cuda_runtime.h>
#include <cstdint>

// ConvTranspose2d(64->64,k4,s2,p1)+bias+mish+(+0.5,clip,*2) via mma.sync tf32.
// y[p,oc] = sum_k A[p,k]*B[oc,k], k = (b*2+a)*64 + ic, K=256.
//   pixel p=(ohi,m): oh = ph+4*tglob+2*ohi, ow = 2m+pw ; Rb = 2*tglob+ph
//   A[p,k] = x[n, ic, Rb+ohi-a, m+pw-b]  (zero OOB), B[oc,k]=w[oc,ic,(1-ph)+2a,(1-pw)+2b]
// 5-slot input-row ring (slot=rg%5, rows 256B = 64 ic, swizzle (j&15)<<4, OOB j->ZROW).
// Staging via cp.async 4B (zfill OOB rows); lane map (ic_lo,j_lo) -> conflict-free STS.
// A raw f32 (HW tf32 truncation), B cvt.rn.tf32.
// Work unit = 4 tiles: 512 units/ph, 74 slots -> max 28 tiles/CTA. Grid 148.
// Epilogue: ys double-buffered IN the 2 dead ring slots (16KB each, XOR swizzle),
// 4 chunks x 16oc, all 16 warps per chunk, store(q) overlapped with write(q+1).

#define NT 512
#define SM_B    256
#define SM_RING (SM_B + 131072)            // 131328
#define ZROW    320
#define SMEM_TOTAL (SM_RING + 321 * 256)   // 213504

static __device__ __forceinline__ uint32_t s2u(const void* p) {
    uint32_t a;
    asm("{ .reg .u64 t; cvta.to.shared.u64 t, %1; cvt.u32.u64 %0, t; }" : "=r"(a) : "l"(p));
    return a;
}
static __device__ __forceinline__ uint32_t cvt_tf32(float f) {
    uint32_t r; asm("cvt.rn.tf32.f32 %0, %1;" : "=r"(r) : "f"(f)); return r;
}
static __device__ __forceinline__ void sts32(uint32_t addr, uint32_t v) {
    asm volatile("st.shared.b32 [%0], %1;" :: "r"(addr), "r"(v) : "memory");
}
static __device__ __forceinline__ void cpasync4(uint32_t dst, const void* src, int sz) {
    asm volatile("cp.async.ca.shared.global [%0], [%1], 4, %2;"
                 :: "r"(dst), "l"(src), "r"(sz) : "memory");
}
static __device__ __forceinline__ void ldsm4(uint32_t* r, uint32_t addr) {
    asm volatile("ldmatrix.sync.aligned.m8n8.x4.shared.b16 {%0,%1,%2,%3}, [%4];"
                 : "=r"(r[0]), "=r"(r[1]), "=r"(r[2]), "=r"(r[3]) : "r"(addr));
}
static __device__ __forceinline__ void mma8(float* d, const uint32_t* a,
                                            uint32_t b0, uint32_t b1) {
    asm volatile("mma.sync.aligned.m16n8k8.row.col.f32.tf32.tf32.f32 "
                 "{%0,%1,%2,%3}, {%4,%5,%6,%7}, {%8,%9}, {%0,%1,%2,%3};"
                 : "+f"(d[0]), "+f"(d[1]), "+f"(d[2]), "+f"(d[3])
                 : "r"(a[0]), "r"(a[1]), "r"(a[2]), "r"(a[3]), "r"(b0), "r"(b1));
}
__device__ __forceinline__ float postop(float y) {
    // mish(y) = y*(t^2+2t)/(t^2+2t+2), t=e^y ; then +0.5, clip[-1,1], *2
    float t = __expf(fminf(y, 30.0f));
    float u = t * (t + 2.0f);
    float mish = y * __fdividef(u, u + 2.0f);
    float v = fminf(fmaxf(mish + 0.5f, -1.0f), 1.0f);
    return v * 2.0f;
}
// ys address inside a dead ring slot: 32 rows x 512B, 16B-chunk XOR swizzle
static __device__ __forceinline__ uint32_t ysaddr(uint32_t base, int row, int p) {
    return base + (uint32_t)row * 512 + ((((uint32_t)p >> 2) ^ (uint32_t)(row & 31)) << 4)
         + (((uint32_t)p & 3) << 2);
}

// stage nrows rows starting at rg0 into ring via cp.async (zfill OOB)
static __device__ __forceinline__ void stage_rows(const float* xn, int rg0, int nrows,
                                                  uint32_t sb, int tid) {
    const int total = nrows * 4096;
#pragma unroll 4
    for (int idx = tid; idx < total; idx += NT) {
        int j  = (idx & 7) | (((idx >> 5) & 7) << 3);
        int ic = ((idx >> 3) & 3) | (((idx >> 8) & 15) << 2);
        int rr = idx >> 12;
        int rg = rg0 + rr;
        int rgc = rg < 0 ? 0 : (rg > 63 ? 63 : rg);
        const float* src = xn + (ic * 64 + rgc) * 64 + j;
        int row = ((rg + 5) % 5) * 64 + j;
        uint32_t dst = sb + SM_RING + row * 256
                     + (((uint32_t)ic << 2) ^ (((uint32_t)j & 15) << 4));
        int sz = ((unsigned)rg < 64u) ? 4 : 0;
        cpasync4(dst, src, sz);
    }
}

__global__ __launch_bounds__(NT, 1)
void convt_mma_kernel(const float* __restrict__ x,
                      const float* __restrict__ weight,
                      const float* __restrict__ bias,
                      float* __restrict__ out) {
    extern __shared__ char smem[];
    const uint32_t sb = s2u(smem);
    const int tid  = threadIdx.x;
    const int warp = tid >> 5;
    const int lane = tid & 31;
    const int ph   = blockIdx.x & 1;
    const int slot = blockIdx.x >> 1;      // 0..73

    if (tid < 64) ((float*)smem)[tid] = bias[tid];

    // ---- stage B once: row = pw*64 + oc (1024B), byte = k*4 ^ ((oc&7)<<4) ----
    for (int it = 0; it < 64; it++) {
        int idx = tid + it * NT;           // 0..32767
        int pw = idx >> 14;
        int oc = (idx >> 8) & 63;
        int k  = idx & 255;
        int g = k >> 6, ic = k & 63, a = g & 1, b = g >> 1;
        int kh = (1 - ph) + 2 * a;
        int kw = (1 - pw) + 2 * b;
        float f = __ldg(weight + ((oc * 64 + ic) << 4) + (kh << 2) + kw);
        uint32_t byte = ((uint32_t)(k << 2)) ^ ((uint32_t)(oc & 7) << 4);
        sts32(sb + SM_B + (pw * 64 + oc) * 1024 + byte, cvt_tf32(f));
    }
    if (tid < 64) sts32(sb + SM_RING + ZROW * 256 + tid * 4, 0u);   // zero row

    // warp roles: pw | och | mq
    const int pw  = warp >> 3;
    const int och = (warp >> 2) & 1;
    const int mq  = warp & 3;
    const int p0  = 32 * mq;
    const int ohi = mq >> 1;
    const int msub0 = 32 * (mq & 1);

    const int l15 = lane & 15;
    const int lhi = lane >> 4;
    const int oc_l = (lane & 7) + 8 * lhi;
    const uint32_t khalf = (uint32_t)((lane >> 3) & 1) << 4;
    const uint32_t swzB  = (uint32_t)(lane & 7) << 4;
    uint32_t rbB[2];
#pragma unroll
    for (int jp = 0; jp < 2; jp++)
        rbB[jp] = sb + SM_B + (uint32_t)(pw * 64 + 32 * och + 16 * jp + oc_l) * 1024;

    const int gL = lane >> 2, tg = lane & 3;
    const float* bsm = (const float*)smem;

    for (int u = slot; u < 512; u += 74) {
        const int n  = u >> 3;
        const int uh = u & 7;
        const int Rb0 = 8 * uh + ph;
        const float* xn = x + (size_t)n * (64 * 64 * 64);

        // ---- prologue: rows Rb0-1..Rb0+1 ----
        stage_rows(xn, Rb0 - 1, 3, sb, tid);
        asm volatile("cp.async.commit_group;" ::: "memory");
        asm volatile("cp.async.wait_group 0;" ::: "memory");
        __syncthreads();

        for (int tl = 0; tl < 4; tl++) {
            const int Rb = Rb0 + 2 * tl;
            const int tglob = 4 * uh + tl;

            // ---- phase A: async-stage rows Rb+2, Rb+3 (next tile) ----
            if (tl < 3) {
                stage_rows(xn, Rb + 2, 2, sb, tid);
                asm volatile("cp.async.commit_group;" ::: "memory");
            }

            // ---- phase B: mma from slots (Rb-1, Rb, Rb+1) ----
            float acc[2][4][4];
#pragma unroll
            for (int i = 0; i < 2; i++)
#pragma unroll
                for (int j = 0; j < 4; j++)
#pragma unroll
                    for (int e = 0; e < 4; e++) acc[i][j][e] = 0.0f;

#pragma unroll
            for (int g = 0; g < 4; g++) {
                const int a = g & 1, b = g >> 1;
                const int rgA = Rb + ohi - a;
                const int slotA = (rgA + 5) % 5;
                const int jA = msub0 + pw - b + l15;
                const int rowL0 = ((unsigned)jA < 64u) ? slotA * 64 + jA : ZROW;
                const int rowL1 = ((unsigned)(jA + 16) < 64u) ? slotA * 64 + jA + 16 : ZROW;
                const uint32_t base0 = sb + SM_RING + (uint32_t)rowL0 * 256;
                const uint32_t base1 = sb + SM_RING + (uint32_t)rowL1 * 256;
                const uint32_t r0 = (uint32_t)(rowL0 & 15);
                const uint32_t r1 = (uint32_t)(rowL1 & 15);
                const uint32_t kb0 = ((uint32_t)g << 8) + khalf;

#pragma unroll
                for (int s8 = 0; s8 < 8; s8++) {
                    const uint32_t ch = (uint32_t)(s8 << 1) + (uint32_t)lhi;
                    uint32_t Af0[4], Af1[4];
                    ldsm4(Af0, base0 + ((ch ^ r0) << 4));
                    ldsm4(Af1, base1 + ((ch ^ r1) << 4));
                    const uint32_t kb = (kb0 + ((uint32_t)s8 << 5)) ^ swzB;
                    uint32_t Bf[2][4];
                    ldsm4(Bf[0], rbB[0] + kb);
                    ldsm4(Bf[1], rbB[1] + kb);
#pragma unroll
                    for (int jp = 0; jp < 2; jp++) {
                        mma8(acc[0][2 * jp],     Af0, Bf[jp][0], Bf[jp][1]);
                        mma8(acc[0][2 * jp + 1], Af0, Bf[jp][2], Bf[jp][3]);
                        mma8(acc[1][2 * jp],     Af1, Bf[jp][0], Bf[jp][1]);
                        mma8(acc[1][2 * jp + 1], Af1, Bf[jp][2], Bf[jp][3]);
                    }
                }
            }
            __syncthreads();   // all warps done reading ring slots (Rb-1)%5, Rb%5

            // ---- phase C: ys double-buffer in dead slots, 4 chunks x 16oc ----
            const uint32_t ysA = sb + SM_RING + (uint32_t)(((Rb + 4) % 5) * 16384);
            const uint32_t ysB = sb + SM_RING + (uint32_t)((Rb % 5) * 16384);
            const int rowc = pw * 16 + 8 * och + 2 * tg;   // ys row for this thread's oc

#define WRITE_CHUNK(q, base) do {                                            \
    const int occ_ = 32 * och + 8 * (q) + 2 * tg;                            \
    const float b0v_ = bsm[occ_], b1v_ = bsm[occ_ + 1];                      \
    _Pragma("unroll")                                                        \
    for (int i_ = 0; i_ < 2; i_++) {                                         \
        const int pr_ = p0 + 16 * i_ + gL;                                   \
        sts32(ysaddr((base), rowc,     pr_),     __float_as_uint(postop(acc[i_][q][0] + b0v_))); \
        sts32(ysaddr((base), rowc + 1, pr_),     __float_as_uint(postop(acc[i_][q][1] + b1v_))); \
        sts32(ysaddr((base), rowc,     pr_ + 8), __float_as_uint(postop(acc[i_][q][2] + b0v_))); \
        sts32(ysaddr((base), rowc + 1, pr_ + 8), __float_as_uint(postop(acc[i_][q][3] + b1v_))); \
    } } while (0)

#define STORE_CHUNK(q, base) do {                                            \
    const char* yb_ = smem + ((base) - sb);                                  \
    _Pragma("unroll")                                                        \
    for (int it_ = 0; it_ < 2; it_++) {                                      \
        int vid_ = tid + it_ * NT;                                           \
        int ow4_ = vid_ & 31;                                                \
        int rw_  = vid_ >> 5;                                                \
        int oh2_ = rw_ & 1;                                                  \
        int ocx_ = rw_ >> 1;                                                 \
        int oc_  = 32 * (ocx_ >> 3) + 8 * (q) + (ocx_ & 7);                  \
        int p_   = oh2_ * 64 + 2 * ow4_;                                     \
        float4 v_;                                                           \
        v_.x = *(const float*)(yb_ + (ysaddr(0u, ocx_,      p_)));           \
        v_.y = *(const float*)(yb_ + (ysaddr(0u, 16 + ocx_, p_)));           \
        v_.z = *(const float*)(yb_ + (ysaddr(0u, ocx_,      p_ + 1)));       \
        v_.w = *(const float*)(yb_ + (ysaddr(0u, 16 + ocx_, p_ + 1)));       \
        int oh_ = ph + 4 * tglob + 2 * oh2_;                                 \
        *(float4*)(out + (((size_t)n * 64 + oc_) * 128 + oh_) * 128 + 4 * ow4_) = v_; \
    } } while (0)

            WRITE_CHUNK(0, ysA);
            __syncthreads();
            STORE_CHUNK(0, ysA); WRITE_CHUNK(1, ysB);
            __syncthreads();
            STORE_CHUNK(1, ysB); WRITE_CHUNK(2, ysA);
            __syncthreads();
            STORE_CHUNK(2, ysA); WRITE_CHUNK(3, ysB);
            __syncthreads();
            STORE_CHUNK(3, ysB);
            asm volatile("cp.async.wait_group 0;" ::: "memory");
            __syncthreads();   // ring writes visible; ys slots free for restage
#undef WRITE_CHUNK
#undef STORE_CHUNK
        }
    }
}

extern "C" void kernel_launch(void* const* d_in, const int* in_sizes, int n_in,
                              void* d_out, int out_size) {
    const float* x      = (const float*)d_in[0];
    const float* weight = (const float*)d_in[1];
    const float* bias   = (const float*)d_in[2];
    float* out          = (float*)d_out;

    cudaFuncSetAttribute(convt_mma_kernel,
                         cudaFuncAttributeMaxDynamicSharedMemorySize, SMEM_TOTAL);
    convt_mma_kernel<<<148, NT, SMEM_TOTAL>>>(x, weight, bias, out);
}

// round 11
// speedup vs baseline: 3.2373x; 1.3955x over previous
#include <cuda_runtime.h>
#include <cstdint>

// ConvTranspose2d(64->64,k4,s2,p1)+bias+mish+(+0.5,clip,*2) via mma.sync fp16 (f32 accum).
// y[p,oc] = sum_k A[p,k]*B[oc,k], k = (b*2+a)*64 + ic, K=256.
//   pixel p=(ohi,m): oh = ph+4*tglob+2*ohi, ow = 2m+pw ; Rb = 2*tglob+ph
//   A[p,k] = x[n, ic, Rb+ohi-a, m+pw-b]  (zero OOB), B[oc,k]=w[oc,ic,(1-ph)+2a,(1-pw)+2b]
// fp16 == tf32 precision here (10-bit mantissa, data in range), 2x MMA throughput,
// half the SMEM/LDSM traffic. 5-slot fp16 row ring (row=slot*64+j, 128B = 64 ic,
// swizzle 16B-chunk ^(j&7)<<4, OOB j -> ZROW). Staging: LDG.32 ic-pair -> cvt.rn.f16x2
// -> STS.32. Work unit = 4 tiles (512 units/ph, 74 slots). Grid 148, 512 thr,
// 16 warps = (pw, och, mq), warp tile 32px x 32oc, 16 k16-steps.
// Epilogue: dedicated 2x16KB ys, 4 chunks x 16oc, store(q) overlaps write(q+1).

#define NT 512
#define SM_B    256
#define SM_RING (SM_B + 65536)             // 65792
#define ZROW    320
#define SM_YS   (SM_RING + 321 * 128)      // 106880
#define SMEM_TOTAL (SM_YS + 32768)         // 139648

static __device__ __forceinline__ uint32_t s2u(const void* p) {
    uint32_t a;
    asm("{ .reg .u64 t; cvta.to.shared.u64 t, %1; cvt.u32.u64 %0, t; }" : "=r"(a) : "l"(p));
    return a;
}
static __device__ __forceinline__ uint32_t f2h2(float lo, float hi) {
    uint32_t r;
    asm("cvt.rn.f16x2.f32 %0, %1, %2;" : "=r"(r) : "f"(hi), "f"(lo));
    return r;
}
static __device__ __forceinline__ void sts32(uint32_t addr, uint32_t v) {
    asm volatile("st.shared.b32 [%0], %1;" :: "r"(addr), "r"(v) : "memory");
}
static __device__ __forceinline__ void ldsm4(uint32_t* r, uint32_t addr) {
    asm volatile("ldmatrix.sync.aligned.m8n8.x4.shared.b16 {%0,%1,%2,%3}, [%4];"
                 : "=r"(r[0]), "=r"(r[1]), "=r"(r[2]), "=r"(r[3]) : "r"(addr));
}
static __device__ __forceinline__ void mma16(float* d, const uint32_t* a,
                                             uint32_t b0, uint32_t b1) {
    asm volatile("mma.sync.aligned.m16n8k16.row.col.f32.f16.f16.f32 "
                 "{%0,%1,%2,%3}, {%4,%5,%6,%7}, {%8,%9}, {%0,%1,%2,%3};"
                 : "+f"(d[0]), "+f"(d[1]), "+f"(d[2]), "+f"(d[3])
                 : "r"(a[0]), "r"(a[1]), "r"(a[2]), "r"(a[3]), "r"(b0), "r"(b1));
}
__device__ __forceinline__ float postop(float y) {
    // mish(y) = y*(t^2+2t)/(t^2+2t+2), t=e^y ; then +0.5, clip[-1,1], *2
    float t = __expf(fminf(y, 30.0f));
    float u = t * (t + 2.0f);
    float mish = y * __fdividef(u, u + 2.0f);
    float v = fminf(fmaxf(mish + 0.5f, -1.0f), 1.0f);
    return v * 2.0f;
}
// ys: 32 rows x 512B, 16B-chunk XOR swizzle by (row&31)
static __device__ __forceinline__ uint32_t ysaddr(uint32_t base, int row, int p) {
    return base + (uint32_t)row * 512 + ((((uint32_t)p >> 2) ^ (uint32_t)(row & 31)) << 4)
         + (((uint32_t)p & 3) << 2);
}

// stage nrows rows starting at rg0: LDG.32 ic-pair -> f16x2 -> STS.32
static __device__ __forceinline__ void stage_rows(const float* xn, int rg0, int nrows,
                                                  uint32_t sb, int tid) {
    const int total = nrows * 2048;        // pairs: 32 icp x 64 j per row
#pragma unroll 4
    for (int idx = tid; idx < total; idx += NT) {
        int j   = idx & 63;
        int icp = (idx >> 6) & 31;
        int rr  = idx >> 11;
        int rg  = rg0 + rr;
        float v0 = 0.0f, v1 = 0.0f;
        if ((unsigned)rg < 64u) {
            const float* p0 = xn + ((2 * icp) * 64 + rg) * 64 + j;
            v0 = __ldg(p0);
            v1 = __ldg(p0 + 4096);
        }
        int row = ((rg + 5) % 5) * 64 + j;
        uint32_t dst = sb + SM_RING + row * 128
                     + (((uint32_t)icp << 2) ^ (((uint32_t)j & 7) << 4));
        sts32(dst, f2h2(v0, v1));
    }
}

__global__ __launch_bounds__(NT, 1)
void convt_mma_kernel(const float* __restrict__ x,
                      const float* __restrict__ weight,
                      const float* __restrict__ bias,
                      float* __restrict__ out) {
    extern __shared__ char smem[];
    const uint32_t sb = s2u(smem);
    const int tid  = threadIdx.x;
    const int warp = tid >> 5;
    const int lane = tid & 31;
    const int ph   = blockIdx.x & 1;
    const int slot = blockIdx.x >> 1;      // 0..73

    if (tid < 64) ((float*)smem)[tid] = bias[tid];

    // ---- stage B once (fp16): row = pw*64+oc (512B), word kp: byte = kp*4 ^ ((oc&7)<<4) ----
    for (int it = 0; it < 32; it++) {
        int idx = tid + it * NT;           // 0..16383 (k-pairs)
        int kp = idx & 127;                // k0 = 2*kp
        int oc = (idx >> 7) & 63;
        int pw = idx >> 13;
        int k0 = 2 * kp;
        int g = k0 >> 6, ic = k0 & 63, a = g & 1, b = g >> 1;
        int kh = (1 - ph) + 2 * a;
        int kw = (1 - pw) + 2 * b;
        const float* wp = weight + ((oc * 64 + ic) << 4) + (kh << 2) + kw;
        float f0 = __ldg(wp);
        float f1 = __ldg(wp + 16);         // ic+1, same (kh,kw)
        uint32_t byte = ((uint32_t)(kp << 2)) ^ ((uint32_t)(oc & 7) << 4);
        sts32(sb + SM_B + (pw * 64 + oc) * 512 + byte, f2h2(f0, f1));
    }
    if (tid < 32) sts32(sb + SM_RING + ZROW * 128 + tid * 4, 0u);   // zero row

    // warp roles: pw | och | mq
    const int pw  = warp >> 3;
    const int och = (warp >> 2) & 1;
    const int mq  = warp & 3;
    const int p0  = 32 * mq;
    const int ohi = mq >> 1;
    const int msub0 = 32 * (mq & 1);

    const int l15 = lane & 15;
    const int lhi = lane >> 4;
    const int oc_l = (lane & 7) + 8 * lhi;
    const uint32_t khalf = (uint32_t)((lane >> 3) & 1) << 4;
    const uint32_t swzB  = (uint32_t)(lane & 7) << 4;
    uint32_t rbB[2];
#pragma unroll
    for (int jp = 0; jp < 2; jp++)
        rbB[jp] = sb + SM_B + (uint32_t)(pw * 64 + 32 * och + 16 * jp + oc_l) * 512;

    const int gL = lane >> 2, tg = lane & 3;
    const float* bsm = (const float*)smem;

    for (int u = slot; u < 512; u += 74) {
        const int n  = u >> 3;
        const int uh = u & 7;
        const int Rb0 = 8 * uh + ph;
        const float* xn = x + (size_t)n * (64 * 64 * 64);

        // ---- prologue: rows Rb0-1..Rb0+1 ----
        stage_rows(xn, Rb0 - 1, 3, sb, tid);
        __syncthreads();

        for (int tl = 0; tl < 4; tl++) {
            const int Rb = Rb0 + 2 * tl;
            const int tglob = 4 * uh + tl;

            // ---- phase A: stage rows Rb+2, Rb+3 (next tile) ----
            if (tl < 3) stage_rows(xn, Rb + 2, 2, sb, tid);

            // ---- phase B: mma from slots (Rb-1, Rb, Rb+1), 16 k16-steps ----
            float acc[2][4][4];
#pragma unroll
            for (int i = 0; i < 2; i++)
#pragma unroll
                for (int j = 0; j < 4; j++)
#pragma unroll
                    for (int e = 0; e < 4; e++) acc[i][j][e] = 0.0f;

#pragma unroll
            for (int g = 0; g < 4; g++) {
                const int a = g & 1, b = g >> 1;
                const int rgA = Rb + ohi - a;
                const int slotA = (rgA + 5) % 5;
                const int jA = msub0 + pw - b + l15;
                const int rowL0 = ((unsigned)jA < 64u) ? slotA * 64 + jA : ZROW;
                const int rowL1 = ((unsigned)(jA + 16) < 64u) ? slotA * 64 + jA + 16 : ZROW;
                const uint32_t base0 = sb + SM_RING + (uint32_t)rowL0 * 128;
                const uint32_t base1 = sb + SM_RING + (uint32_t)rowL1 * 128;
                const uint32_t r0 = (uint32_t)(rowL0 & 7);
                const uint32_t r1 = (uint32_t)(rowL1 & 7);
                const uint32_t kbg = (uint32_t)g << 7;   // g*128 bytes

#pragma unroll
                for (int s = 0; s < 4; s++) {
                    const uint32_t ch = (uint32_t)(s << 1) + (uint32_t)lhi;  // 0..7
                    uint32_t Af0[4], Af1[4];
                    ldsm4(Af0, base0 + ((ch ^ r0) << 4));
                    ldsm4(Af1, base1 + ((ch ^ r1) << 4));
                    const uint32_t kb = (kbg + ((uint32_t)s << 5) + khalf) ^ swzB;
                    uint32_t Bf0[4], Bf1[4];
                    ldsm4(Bf0, rbB[0] + kb);
                    ldsm4(Bf1, rbB[1] + kb);
                    mma16(acc[0][0], Af0, Bf0[0], Bf0[1]);
                    mma16(acc[0][1], Af0, Bf0[2], Bf0[3]);
                    mma16(acc[0][2], Af0, Bf1[0], Bf1[1]);
                    mma16(acc[0][3], Af0, Bf1[2], Bf1[3]);
                    mma16(acc[1][0], Af1, Bf0[0], Bf0[1]);
                    mma16(acc[1][1], Af1, Bf0[2], Bf0[3]);
                    mma16(acc[1][2], Af1, Bf1[0], Bf1[1]);
                    mma16(acc[1][3], Af1, Bf1[2], Bf1[3]);
                }
            }
            __syncthreads();   // ring reads done; staging STS visible next tile

            // ---- phase C: ys double-buffer (dedicated), 4 chunks x 16oc ----
            const uint32_t ysA = sb + SM_YS;
            const uint32_t ysB = sb + SM_YS + 16384;
            const int rowc = pw * 16 + 8 * och + 2 * tg;

#define WRITE_CHUNK(q, base) do {                                            \
    const int occ_ = 32 * och + 8 * (q) + 2 * tg;                            \
    const float b0v_ = bsm[occ_], b1v_ = bsm[occ_ + 1];                      \
    _Pragma("unroll")                                                        \
    for (int i_ = 0; i_ < 2; i_++) {                                         \
        const int pr_ = p0 + 16 * i_ + gL;                                   \
        sts32(ysaddr((base), rowc,     pr_),     __float_as_uint(postop(acc[i_][q][0] + b0v_))); \
        sts32(ysaddr((base), rowc + 1, pr_),     __float_as_uint(postop(acc[i_][q][1] + b1v_))); \
        sts32(ysaddr((base), rowc,     pr_ + 8), __float_as_uint(postop(acc[i_][q][2] + b0v_))); \
        sts32(ysaddr((base), rowc + 1, pr_ + 8), __float_as_uint(postop(acc[i_][q][3] + b1v_))); \
    } } while (0)

#define STORE_CHUNK(q, base) do {                                            \
    const char* yb_ = smem + ((base) - sb);                                  \
    _Pragma("unroll")                                                        \
    for (int it_ = 0; it_ < 2; it_++) {                                      \
        int vid_ = tid + it_ * NT;                                           \
        int ow4_ = vid_ & 31;                                                \
        int rw_  = vid_ >> 5;                                                \
        int oh2_ = rw_ & 1;                                                  \
        int ocx_ = rw_ >> 1;                                                 \
        int oc_  = 32 * (ocx_ >> 3) + 8 * (q) + (ocx_ & 7);                  \
        int p_   = oh2_ * 64 + 2 * ow4_;                                     \
        float4 v_;                                                           \
        v_.x = *(const float*)(yb_ + (ysaddr(0u, ocx_,      p_)));           \
        v_.y = *(const float*)(yb_ + (ysaddr(0u, 16 + ocx_, p_)));           \
        v_.z = *(const float*)(yb_ + (ysaddr(0u, ocx_,      p_ + 1)));       \
        v_.w = *(const float*)(yb_ + (ysaddr(0u, 16 + ocx_, p_ + 1)));       \
        int oh_ = ph + 4 * tglob + 2 * oh2_;                                 \
        *(float4*)(out + (((size_t)n * 64 + oc_) * 128 + oh_) * 128 + 4 * ow4_) = v_; \
    } } while (0)

            WRITE_CHUNK(0, ysA);
            __syncthreads();
            STORE_CHUNK(0, ysA); WRITE_CHUNK(1, ysB);
            __syncthreads();
            STORE_CHUNK(1, ysB); WRITE_CHUNK(2, ysA);
            __syncthreads();
            STORE_CHUNK(2, ysA); WRITE_CHUNK(3, ysB);
            __syncthreads();
            STORE_CHUNK(3, ysB);
            __syncthreads();
#undef WRITE_CHUNK
#undef STORE_CHUNK
        }
    }
}

extern "C" void kernel_launch(void* const* d_in, const int* in_sizes, int n_in,
                              void* d_out, int out_size) {
    const float* x      = (const float*)d_in[0];
    const float* weight = (const float*)d_in[1];
    const float* bias   = (const float*)d_in[2];
    float* out          = (float*)d_out;

    cudaFuncSetAttribute(convt_mma_kernel,
                         cudaFuncAttributeMaxDynamicSharedMemorySize, SMEM_TOTAL);
    convt_mma_kernel<<<148, NT, SMEM_TOTAL>>>(x, weight, bias, out);
}